// round 8
// baseline (speedup 1.0000x reference)
#include <cuda_runtime.h>
#include <cstdint>
#include <math.h>

#define DM   1024
#define NH   16
#define HD   64
#define BSZ  2
#define SL   1024
#define NTOK (BSZ*SL)   // 2048
#define NBH  (BSZ*NH)   // 32

// ---------------- device scratch (no cudaMalloc allowed) ----------------
// token-major: [token][DM]  (head h occupies cols h*64..h*64+63)
__device__ float g_q[NTOK*DM];
__device__ float g_k[NTOK*DM];
__device__ float g_v[NTOK*DM];
__device__ float g_o[NTOK*DM];
__device__ float g_beta[NBH*SL];        // [bh][t]
__device__ float g_normed[NTOK*DM];

// ---------------- helpers ------------------------------------------------
__device__ __forceinline__ uint32_t f2tf32(float f) {
    uint32_t r;
    asm("cvt.rna.tf32.f32 %0, %1;" : "=r"(r) : "f"(f));
    return r;
}
__device__ __forceinline__ void mma_tf32(float* d, const uint32_t* a, const uint32_t* b) {
    asm volatile(
        "mma.sync.aligned.m16n8k8.row.col.f32.tf32.tf32.f32 "
        "{%0,%1,%2,%3}, {%4,%5,%6,%7}, {%8,%9}, {%0,%1,%2,%3};\n"
        : "+f"(d[0]), "+f"(d[1]), "+f"(d[2]), "+f"(d[3])
        : "r"(a[0]), "r"(a[1]), "r"(a[2]), "r"(a[3]), "r"(b[0]), "r"(b[1]));
}
__device__ __forceinline__ float silu(float x) {
    return x / (1.f + __expf(-x));
}
// packed f32x2 fma: d = a*b + c  (componentwise on 2 packed floats)
__device__ __forceinline__ unsigned long long fma2(
    unsigned long long a, unsigned long long b, unsigned long long c) {
    unsigned long long d;
    asm("fma.rn.f32x2 %0, %1, %2, %3;" : "=l"(d) : "l"(a), "l"(b), "l"(c));
    return d;
}
__device__ __forceinline__ unsigned long long pack2(float lo, float hi) {
    unsigned long long r;
    asm("mov.b64 %0, {%1, %2};" : "=l"(r) : "f"(lo), "f"(hi));
    return r;
}
__device__ __forceinline__ float hsum2(unsigned long long p) {
    float lo, hi;
    asm("mov.b64 {%0, %1}, %2;" : "=f"(lo), "=f"(hi) : "l"(p));
    return lo + hi;
}

// ================= 3xTF32 mma.sync GEMM: C = A @ W^T =====================
// Block tile 128x128, 8 warps (2x4 grid of 64x32 warp tiles).
// Single-buffered SMEM stage (K=16) holding hi/lo tf32 split tiles,
// global loads prefetched into registers. 3 MMAs per fragment pair:
// hi*hi + hi*lo + lo*hi  (effective ~fp32 precision).
// mode 0: A=x, weights Wq/Wk/Wv; epilogue silu; store token-major q/k/v.
//         grid (24,16).
// mode 1: A=g_normed, W0=Wo; plain store to Cout. grid (8,16).
#define KST   16
#define NSTG  (DM/KST)   // 64
#define SSTR  20         // smem row stride (floats)

__global__ __launch_bounds__(256, 1) void gemm_mma(
    const float* __restrict__ A,
    const float* __restrict__ W0,
    const float* __restrict__ W1,
    const float* __restrict__ W2,
    float* __restrict__ Cout, int mode)
{
    __shared__ __align__(16) float Ah[128*SSTR];
    __shared__ __align__(16) float Al[128*SSTR];
    __shared__ __align__(16) float Bh[128*SSTR];
    __shared__ __align__(16) float Bl[128*SSTR];

    const int tid  = threadIdx.x;
    const int lane = tid & 31, wid = tid >> 5;
    const int gid  = lane >> 2, tg = lane & 3;
    const int wm   = wid & 1,  wn  = wid >> 1;   // 2 x 4 warp grid

    int which = 0, n0;
    const float* B;
    if (mode == 0) {
        which = blockIdx.x >> 3;
        n0 = (blockIdx.x & 7) * 128;
        B = (which == 0) ? W0 : (which == 1) ? W1 : W2;
    } else {
        n0 = blockIdx.x * 128;
        B = W0;
    }
    const float* Ap = (mode == 1) ? g_normed : A;
    const int m0 = blockIdx.y * 128;

    float acc[4][4][4];
#pragma unroll
    for (int mi = 0; mi < 4; mi++)
#pragma unroll
        for (int nj = 0; nj < 4; nj++)
#pragma unroll
            for (int e = 0; e < 4; e++) acc[mi][nj][e] = 0.f;

    // staging: each thread owns rows r0 and r0+64, 4 floats at col c40*4
    const int r0  = tid >> 2;
    const int c40 = tid & 3;
    const float* Aptr  = Ap + (size_t)(m0 + r0) * DM + c40 * 4;
    const float* Aptr2 = Aptr + (size_t)64 * DM;
    const float* Bptr  = B  + (size_t)(n0 + r0) * DM + c40 * 4;
    const float* Bptr2 = Bptr + (size_t)64 * DM;

    float4 ra0, ra1, rb0, rb1;
    auto ld = [&](int kt) {
        ra0 = *(const float4*)(Aptr  + kt * KST);
        ra1 = *(const float4*)(Aptr2 + kt * KST);
        rb0 = *(const float4*)(Bptr  + kt * KST);
        rb1 = *(const float4*)(Bptr2 + kt * KST);
    };
    // split one float4 into hi/lo tf32 and store to the two tiles
    auto split_st = [&](float4 v, float* th, float* tl, int off) {
        uint4 h, l;
        h.x = f2tf32(v.x); l.x = f2tf32(v.x - __uint_as_float(h.x));
        h.y = f2tf32(v.y); l.y = f2tf32(v.y - __uint_as_float(h.y));
        h.z = f2tf32(v.z); l.z = f2tf32(v.z - __uint_as_float(h.z));
        h.w = f2tf32(v.w); l.w = f2tf32(v.w - __uint_as_float(h.w));
        *(uint4*)(th + off) = h;
        *(uint4*)(tl + off) = l;
    };

    ld(0);
    for (int kt = 0; kt < NSTG; kt++) {
        __syncthreads();   // previous stage's MMA reads complete
        split_st(ra0, Ah, Al, r0 * SSTR + c40 * 4);
        split_st(ra1, Ah, Al, (r0 + 64) * SSTR + c40 * 4);
        split_st(rb0, Bh, Bl, r0 * SSTR + c40 * 4);
        split_st(rb1, Bh, Bl, (r0 + 64) * SSTR + c40 * 4);
        if (kt + 1 < NSTG) ld(kt + 1);
        __syncthreads();

#pragma unroll
        for (int k8 = 0; k8 < 2; k8++) {
            const int kc = k8 * 8;
            uint32_t afh[4][4], afl[4][4], bfh[4][2], bfl[4][2];
#pragma unroll
            for (int mi = 0; mi < 4; mi++) {
                int rb = (wm * 64 + mi * 16 + gid) * SSTR + kc + tg;
                afh[mi][0] = __float_as_uint(Ah[rb]);
                afh[mi][1] = __float_as_uint(Ah[rb + 8 * SSTR]);
                afh[mi][2] = __float_as_uint(Ah[rb + 4]);
                afh[mi][3] = __float_as_uint(Ah[rb + 8 * SSTR + 4]);
                afl[mi][0] = __float_as_uint(Al[rb]);
                afl[mi][1] = __float_as_uint(Al[rb + 8 * SSTR]);
                afl[mi][2] = __float_as_uint(Al[rb + 4]);
                afl[mi][3] = __float_as_uint(Al[rb + 8 * SSTR + 4]);
            }
#pragma unroll
            for (int nj = 0; nj < 4; nj++) {
                int nb = (wn * 32 + nj * 8 + gid) * SSTR + kc + tg;
                bfh[nj][0] = __float_as_uint(Bh[nb]);
                bfh[nj][1] = __float_as_uint(Bh[nb + 4]);
                bfl[nj][0] = __float_as_uint(Bl[nb]);
                bfl[nj][1] = __float_as_uint(Bl[nb + 4]);
            }
#pragma unroll
            for (int mi = 0; mi < 4; mi++)
#pragma unroll
                for (int nj = 0; nj < 4; nj++) {
                    mma_tf32(acc[mi][nj], afh[mi], bfh[nj]);
                    mma_tf32(acc[mi][nj], afh[mi], bfl[nj]);
                    mma_tf32(acc[mi][nj], afl[mi], bfh[nj]);
                }
        }
    }

    // ------------- epilogue -------------
    if (mode == 0) {
        float* dst = (which == 0) ? g_q : (which == 1) ? g_k : g_v;
#pragma unroll
        for (int mi = 0; mi < 4; mi++) {
            int r = m0 + wm * 64 + mi * 16 + gid;
#pragma unroll
            for (int nj = 0; nj < 4; nj++) {
                int cb = n0 + wn * 32 + nj * 8 + 2 * tg;
                float2 lo = make_float2(silu(acc[mi][nj][0]), silu(acc[mi][nj][1]));
                float2 hi = make_float2(silu(acc[mi][nj][2]), silu(acc[mi][nj][3]));
                *(float2*)(dst + (size_t)r * DM + cb)       = lo;
                *(float2*)(dst + (size_t)(r + 8) * DM + cb) = hi;
            }
        }
    } else {
#pragma unroll
        for (int mi = 0; mi < 4; mi++) {
            int r = m0 + wm * 64 + mi * 16 + gid;
#pragma unroll
            for (int nj = 0; nj < 4; nj++) {
                int cb = n0 + wn * 32 + nj * 8 + 2 * tg;
                *(float2*)(Cout + (size_t)r * DM + cb) =
                    make_float2(acc[mi][nj][0], acc[mi][nj][1]);
                *(float2*)(Cout + (size_t)(r + 8) * DM + cb) =
                    make_float2(acc[mi][nj][2], acc[mi][nj][3]);
            }
        }
    }
}

// ---------------- beta = 2*sigmoid(x @ Wb^T), per token -----------------
__global__ __launch_bounds__(128) void beta_kernel(
    const float* __restrict__ x, const float* __restrict__ Wb)
{
    __shared__ float xs[DM];
    __shared__ float pp[8][16];
    int m = blockIdx.x;
#pragma unroll
    for (int i = threadIdx.x; i < DM/4; i += 128)
        ((float4*)xs)[i] = ((const float4*)(x + (size_t)m * DM))[i];
    __syncthreads();

    int h = threadIdx.x & 15;
    int slice = threadIdx.x >> 4;
    const float* w = Wb + h * DM;
    float p = 0.f;
    int k0 = slice * 128;
#pragma unroll 4
    for (int kk = 0; kk < 128; kk++) p += xs[k0 + kk] * w[k0 + kk];
    pp[slice][h] = p;
    __syncthreads();
    if (threadIdx.x < 16) {
        float s = 0.f;
#pragma unroll
        for (int j = 0; j < 8; j++) s += pp[j][threadIdx.x];
        float bsig = 2.f / (1.f + expf(-s));
        int b = m >> 10, t = m & 1023;
        g_beta[((b << 4) + threadIdx.x) * SL + t] = bsig;
    }
}

// ---------------- L2-normalize q and k head rows (flat 64-float rows) ---
__global__ __launch_bounds__(256) void l2norm_kernel()
{
    int gw = (blockIdx.x * blockDim.x + threadIdx.x) >> 5;  // warp id
    int lane = threadIdx.x & 31;
    if (gw >= 2 * NTOK * NH) return;
    float* base = (gw < NTOK * NH) ? g_q : g_k;
    int row = gw & (NTOK * NH - 1);
    float2* p = (float2*)(base + (size_t)row * HD) + lane;
    float2 v = *p;
    float ss = v.x * v.x + v.y * v.y;
#pragma unroll
    for (int o = 16; o; o >>= 1) ss += __shfl_xor_sync(0xffffffffu, ss, o);
    float sc = 1.f / (sqrtf(ss) + 1e-6f);
    v.x *= sc; v.y *= sc;
    *p = v;
}

// ---------------- sequential delta scan, 1 block per (b,h) --------------
// thread = (c = tid>>2, seg = tid&3): 4 consecutive lanes own column c.
// Dual register-resident copies of M as packed f32x2 pairs:
//   Mcol[j] = { M[seg*16+2j][c], M[seg*16+2j+1][c] }
//   Mrow[j] = { M[c][seg*16+2j], M[c][seg*16+2j+1] }
// One barrier per token; partial dots reduced with shfl_xor over 4 lanes.
union F4U { float4 f; unsigned long long u[2]; };

__global__ __launch_bounds__(256) void scan_kernel()
{
    int bh = blockIdx.x;
    int b = bh >> 4, h = bh & 15;
    const size_t rowbase = (size_t)b * SL;
    const float* bt = g_beta + (size_t)bh * SL;

    int tid = threadIdx.x;
    int c   = tid >> 2;
    int seg = tid & 3;

    unsigned long long Mcol[8], Mrow[8];
#pragma unroll
    for (int j = 0; j < 8; j++) { Mcol[j] = 0ull; Mrow[j] = 0ull; }

    __shared__ float sq[16][64], sk[16][64], sv[16][64];
    __shared__ float sb[16];
    __shared__ float sdelta[2][64];
    __shared__ float sout[16][64];

    int rr = tid >> 4, c4 = tid & 15;

    for (int t0 = 0; t0 < SL; t0 += 16) {
        __syncthreads();   // prior chunk's sout dump + reads done
        {
            size_t roff = (rowbase + t0 + rr) * DM + h * HD;
            ((float4*)sq)[tid] = ((const float4*)(g_q + roff))[c4];
            ((float4*)sk)[tid] = ((const float4*)(g_k + roff))[c4];
            ((float4*)sv)[tid] = ((const float4*)(g_v + roff))[c4];
        }
        if (tid < 16) sb[tid] = bt[t0 + tid];
        __syncthreads();

#pragma unroll 1
        for (int tt = 0; tt < 16; tt++) {
            F4U kk[4], qq[4];
            kk[0].f = *(const float4*)&sk[tt][seg*16];
            kk[1].f = *(const float4*)&sk[tt][seg*16+4];
            kk[2].f = *(const float4*)&sk[tt][seg*16+8];
            kk[3].f = *(const float4*)&sk[tt][seg*16+12];
            qq[0].f = *(const float4*)&sq[tt][seg*16];
            qq[1].f = *(const float4*)&sq[tt][seg*16+4];
            qq[2].f = *(const float4*)&sq[tt][seg*16+8];
            qq[3].f = *(const float4*)&sq[tt][seg*16+12];

            unsigned long long pr2 = 0ull, po2 = 0ull;
#pragma unroll
            for (int j = 0; j < 8; j++) {
                pr2 = fma2(Mrow[j], kk[j>>1].u[j&1], pr2);
                po2 = fma2(qq[j>>1].u[j&1], Mcol[j], po2);
            }
            float pr = hsum2(pr2);
            float po = hsum2(po2);
            pr += __shfl_xor_sync(0xffffffffu, pr, 1);
            pr += __shfl_xor_sync(0xffffffffu, pr, 2);
            po += __shfl_xor_sync(0xffffffffu, po, 1);
            po += __shfl_xor_sync(0xffffffffu, po, 2);

            float dc = sv[tt][c] - pr;     // delta[c] (all 4 lanes have it)
            int buf = tt & 1;
            if (seg == 0) {
                sdelta[buf][c] = dc;
                sout[tt][c] = po;
            }
            __syncthreads();               // the only barrier per token

            float b_t = sb[tt];
            float bdcs = b_t * dc;
            float brks = b_t * sk[tt][c];
            unsigned long long bdc2 = pack2(bdcs, bdcs);
            unsigned long long brk2 = pack2(brks, brks);

            F4U dd[4];
            dd[0].f = *(const float4*)&sdelta[buf][seg*16];
            dd[1].f = *(const float4*)&sdelta[buf][seg*16+4];
            dd[2].f = *(const float4*)&sdelta[buf][seg*16+8];
            dd[3].f = *(const float4*)&sdelta[buf][seg*16+12];
#pragma unroll
            for (int j = 0; j < 8; j++) {
                Mcol[j] = fma2(kk[j>>1].u[j&1], bdc2, Mcol[j]);
                Mrow[j] = fma2(dd[j>>1].u[j&1], brk2, Mrow[j]);
            }
        }
        // dump sout (tt=15's barrier ordered all writes before here)
        {
            size_t roff = (rowbase + t0 + rr) * DM + h * HD;
            ((float4*)(g_o + roff))[c4] = ((const float4*)sout)[tid];
        }
    }
}

// ---------------- RMSNorm (token-major rows) -> g_normed ----------------
__global__ __launch_bounds__(256) void rms_kernel(const float* __restrict__ rms_w)
{
    __shared__ float red[256];
    int m = blockIdx.x;
    int tid = threadIdx.x;
    int f = tid * 4;
    float4 v4 = *(const float4*)(g_o + (size_t)m * DM + f);
    float ss = v4.x*v4.x + v4.y*v4.y + v4.z*v4.z + v4.w*v4.w;
    red[tid] = ss;
    __syncthreads();
    for (int s = 128; s > 0; s >>= 1) {
        if (tid < s) red[tid] += red[tid + s];
        __syncthreads();
    }
    float inv = rsqrtf(red[0] * (1.f / 1024.f) + 1e-6f);
    float4 w4 = *(const float4*)(rms_w + f);
    float4 r;
    r.x = v4.x * inv * w4.x;
    r.y = v4.y * inv * w4.y;
    r.z = v4.z * inv * w4.z;
    r.w = v4.w * inv * w4.w;
    *(float4*)(g_normed + (size_t)m * DM + f) = r;
}

// ---------------------------- launch ------------------------------------
extern "C" void kernel_launch(void* const* d_in, const int* in_sizes, int n_in,
                              void* d_out, int out_size)
{
    const float* x     = (const float*)d_in[0];
    const float* Wq    = (const float*)d_in[1];
    const float* Wk    = (const float*)d_in[2];
    const float* Wv    = (const float*)d_in[3];
    const float* Wb    = (const float*)d_in[4];
    const float* Wo    = (const float*)d_in[5];
    const float* rms_w = (const float*)d_in[6];
    float* out = (float*)d_out;

    // 1) q/k/v projections (3xTF32 tensor cores) + silu epilogue
    {
        dim3 g(24, 16);
        gemm_mma<<<g, 256>>>(x, Wq, Wk, Wv, nullptr, 0);
    }
    // 2) beta
    beta_kernel<<<NTOK, 128>>>(x, Wb);
    // 3) L2 norm of q and k heads
    l2norm_kernel<<<2 * NTOK * NH / 8, 256>>>();
    // 4) sequential delta scan
    scan_kernel<<<NBH, 256>>>();
    // 5) RMSNorm
    rms_kernel<<<NTOK, 256>>>(rms_w);
    // 6) output projection (3xTF32)
    {
        dim3 g(8, 16);
        gemm_mma<<<g, 256>>>(nullptr, Wo, nullptr, nullptr, out, 1);
    }
}